// round 1
// baseline (speedup 1.0000x reference)
#include <cuda_runtime.h>
#include <cuda_bf16.h>

// GCNet cost-volume + softargmax, specialized:
//   B=1, C=32, H=128, W=256, dmin=min_disp/2, dmax=max_disp/2 (default 0,64)
//
// Output [2C, H, W]:
//   channels [0,C):   softmax over a d-constant vector -> uniform -> mean disparity
//   channels [C,2C):  sliding-window softargmax over feaR via prefix sums:
//       x_d = feaR[c,h,w-d] if 0 <= w-d < W else 0   (cost literally 0, exp(0)=1)
//       out = sum_d d*exp(x_d) / sum_d exp(x_d)
//   With e[j]=exp(feaR[j]), P=prefix(e), Q=prefix(j*e):
//       valid d in [dmin, m], m=min(dmax-1,w)  (w-d<W always for d>=0)
//       j = w-d in [lo,hi], hi=w-dmin, lo=w-m
//       sum_valid e      = dP = P[hi]-P[lo-1]
//       sum_valid d*e    = w*dP - dQ
//       invalid: each contributes exp(0)=1 weight, disparity value d
//       s0 = dP + nInv ; s1 = w*dP - dQ + (sumAll_d - sumValid_d)

#ifndef GC_B
#define GC_B 1
#endif
#define GC_C 32
#define GC_H 128
#define GC_W 256

__global__ __launch_bounds__(GC_W, 4)
void gcnet_softargmax_kernel(const float* __restrict__ feaR,
                             const int* __restrict__ p_min_disp,
                             const int* __restrict__ p_max_disp,
                             float* __restrict__ out)
{
    const int tid = threadIdx.x;          // == w, 0..255
    const int c   = blockIdx.x / GC_H;    // feaR channel 0..31
    const int h   = blockIdx.x % GC_H;

    int min_disp = p_min_disp ? *p_min_disp : 0;
    int max_disp = p_max_disp ? *p_max_disp : 128;
    const int dmin = min_disp / 2;
    const int dmax = max_disp / 2;
    const int D    = dmax - dmin;
    const float meanD = 0.5f * (float)(dmin + dmax - 1);

    // ---- left channels: constant expected disparity (softmax of constant = uniform)
    out[(size_t)c * (GC_H * GC_W) + (size_t)h * GC_W + tid] = meanD;

    // ---- right channels: prefix-sum softargmax
    const float x = feaR[((size_t)c * GC_H + h) * GC_W + tid];
    double e = (double)expf(x);
    double q = (double)tid * e;

    // block-wide inclusive scan of (e, q): warp shfl scan + cross-warp combine
    const unsigned lane = tid & 31u;
    const unsigned wrp  = tid >> 5;       // 8 warps

    #pragma unroll
    for (int off = 1; off < 32; off <<= 1) {
        double te = __shfl_up_sync(0xffffffffu, e, off);
        double tq = __shfl_up_sync(0xffffffffu, q, off);
        if (lane >= (unsigned)off) { e += te; q += tq; }
    }

    __shared__ double wsumE[8], wsumQ[8];
    __shared__ double sP[GC_W], sQ[GC_W];
    if (lane == 31u) { wsumE[wrp] = e; wsumQ[wrp] = q; }
    __syncthreads();

    double addE = 0.0, addQ = 0.0;
    #pragma unroll
    for (int i = 0; i < 8; i++) {
        if ((unsigned)i < wrp) { addE += wsumE[i]; addQ += wsumQ[i]; }
    }
    e += addE; q += addQ;
    sP[tid] = e; sQ[tid] = q;
    __syncthreads();

    const int w = tid;
    const int m = min(dmax - 1, w);       // highest valid disparity (w-d >= 0)
    double s0, s1;
    const double sumAll_d = 0.5 * (double)(dmin + dmax - 1) * (double)D;

    if (m < dmin) {
        // no valid disparity: all D entries are cost 0 -> uniform -> mean
        s0 = (double)D;
        s1 = sumAll_d;
    } else {
        const int hi = w - dmin;          // >= 0 here
        const int lo = w - m;             // >= 0
        const double pb = (lo > 0) ? sP[lo - 1] : 0.0;
        const double qb = (lo > 0) ? sQ[lo - 1] : 0.0;
        const double dP = sP[hi] - pb;
        const double dQ = sQ[hi] - qb;
        const int nValid = m - dmin + 1;
        const int nInv   = D - nValid;
        const double sumValid_d = 0.5 * (double)(m + dmin) * (double)nValid;
        s0 = dP + (double)nInv;
        s1 = (double)w * dP - dQ + (sumAll_d - sumValid_d);
    }

    out[((size_t)(GC_C + c)) * (GC_H * GC_W) + (size_t)h * GC_W + w] = (float)(s1 / s0);
}

extern "C" void kernel_launch(void* const* d_in, const int* in_sizes, int n_in,
                              void* d_out, int out_size)
{
    // metadata order: feaL (unused — left channels are constant), feaR, min_disp, max_disp
    const float* feaR = (const float*)d_in[1];
    const int* pmin = (n_in > 2) ? (const int*)d_in[2] : nullptr;
    const int* pmax = (n_in > 3) ? (const int*)d_in[3] : nullptr;
    float* out = (float*)d_out;

    dim3 grid(GC_C * GC_H);   // one block per (channel,row) of feaR
    dim3 block(GC_W);
    gcnet_softargmax_kernel<<<grid, block>>>(feaR, pmin, pmax, out);
}

// round 4
// speedup vs baseline: 9.7910x; 9.7910x over previous
#include <cuda_runtime.h>
#include <cuda_bf16.h>

// GCNet cost-volume + softargmax, specialized:
//   B=1, C=32, H=128, W=256, dmin=min_disp/2, dmax=max_disp/2 (default 0,64)
//
// Output [2C, H, W]:
//   channels [0,C):   softmax over a d-constant vector -> uniform -> mean disparity
//   channels [C,2C):  sliding-window softargmax over feaR via fp32 prefix sums:
//       x_d = feaR[c,h,w-d] if 0 <= w-d < W else 0   (cost literally 0, exp(0)=1)
//       out = sum_d d*exp(x_d) / sum_d exp(x_d)
//   With e[j]=exp(feaR[j]), P=prefix(e), Q=prefix(j*e):
//       valid d in [dmin, m], m=min(dmax-1,w)
//       j = w-d in [lo,hi], hi=w-dmin, lo=w-m
//       sum_valid e   = dP = P[hi]-P[lo-1]
//       sum_valid d*e = w*dP - dQ
//       invalid: each contributes exp(0)=1 weight, disparity value d
//       s0 = dP + nInv ; s1 = w*dP - dQ + (sumAll_d - sumValid_d)
//
// R1 change: all-fp32 (R0 used fp64 scan -> FP64-pipe bound, 105us with every
// other pipe idle). fp32 halves SHFL count and removes DADD/DMUL/DDIV entirely.
// R2, R3: resubmissions — benches never ran (GPU broker timeouts).

#define GC_C 32
#define GC_H 128
#define GC_W 256

__global__ __launch_bounds__(GC_W)
void gcnet_softargmax_kernel(const float* __restrict__ feaR,
                             const int* __restrict__ p_min_disp,
                             const int* __restrict__ p_max_disp,
                             float* __restrict__ out)
{
    const int tid = threadIdx.x;          // == w, 0..255
    const int c   = blockIdx.x / GC_H;    // feaR channel 0..31
    const int h   = blockIdx.x % GC_H;

    const int min_disp = p_min_disp ? *p_min_disp : 0;
    const int max_disp = p_max_disp ? *p_max_disp : 128;
    const int dmin = min_disp / 2;
    const int dmax = max_disp / 2;
    const int D    = dmax - dmin;
    const float meanD = 0.5f * (float)(dmin + dmax - 1);

    // ---- left channels: constant expected disparity (softmax of constant = uniform)
    out[(size_t)c * (GC_H * GC_W) + (size_t)h * GC_W + tid] = meanD;

    // ---- right channels: prefix-sum softargmax (fp32)
    const float x = feaR[((size_t)c * GC_H + h) * GC_W + tid];
    float e = expf(x);
    float q = (float)tid * e;

    // block-wide inclusive scan of (e, q): warp shfl scan + cross-warp combine
    const unsigned lane = tid & 31u;
    const unsigned wrp  = tid >> 5;       // 8 warps

    #pragma unroll
    for (int off = 1; off < 32; off <<= 1) {
        float te = __shfl_up_sync(0xffffffffu, e, off);
        float tq = __shfl_up_sync(0xffffffffu, q, off);
        if (lane >= (unsigned)off) { e += te; q += tq; }
    }

    __shared__ float wsumE[8], wsumQ[8];
    __shared__ float sP[GC_W], sQ[GC_W];
    if (lane == 31u) { wsumE[wrp] = e; wsumQ[wrp] = q; }
    __syncthreads();

    float addE = 0.0f, addQ = 0.0f;
    #pragma unroll
    for (int i = 0; i < 8; i++) {
        if ((unsigned)i < wrp) { addE += wsumE[i]; addQ += wsumQ[i]; }
    }
    e += addE; q += addQ;
    sP[tid] = e; sQ[tid] = q;
    __syncthreads();

    const int w = tid;
    const int m = min(dmax - 1, w);       // highest valid disparity (w-d >= 0)
    const float sumAll_d = 0.5f * (float)(dmin + dmax - 1) * (float)D;
    float s0, s1;

    if (m < dmin) {
        // no valid disparity: all D entries are cost 0 -> uniform -> mean
        s0 = (float)D;
        s1 = sumAll_d;
    } else {
        const int hi = w - dmin;          // >= 0 here
        const int lo = w - m;             // >= 0
        const float pb = (lo > 0) ? sP[lo - 1] : 0.0f;
        const float qb = (lo > 0) ? sQ[lo - 1] : 0.0f;
        const float dP = sP[hi] - pb;
        const float dQ = sQ[hi] - qb;
        const int nValid = m - dmin + 1;
        const int nInv   = D - nValid;
        const float sumValid_d = 0.5f * (float)(m + dmin) * (float)nValid;
        s0 = dP + (float)nInv;
        s1 = (float)w * dP - dQ + (sumAll_d - sumValid_d);
    }

    out[((size_t)(GC_C + c)) * (GC_H * GC_W) + (size_t)h * GC_W + w] = s1 / s0;
}

extern "C" void kernel_launch(void* const* d_in, const int* in_sizes, int n_in,
                              void* d_out, int out_size)
{
    // metadata order: feaL (unused — left channels are constant), feaR, min_disp, max_disp
    const float* feaR = (const float*)d_in[1];
    const int* pmin = (n_in > 2) ? (const int*)d_in[2] : nullptr;
    const int* pmax = (n_in > 3) ? (const int*)d_in[3] : nullptr;
    float* out = (float*)d_out;

    dim3 grid(GC_C * GC_H);   // one block per (channel,row) of feaR
    dim3 block(GC_W);
    gcnet_softargmax_kernel<<<grid, block>>>(feaR, pmin, pmax, out);
}

// round 5
// speedup vs baseline: 11.7986x; 1.2050x over previous
#include <cuda_runtime.h>
#include <cuda_bf16.h>

// GCNet cost-volume + softargmax, specialized:
//   B=1, C=32, H=128, W=256, dmin=min_disp/2, dmax=max_disp/2 (default 0,64)
//
//   channels [0,C):   softmax over d-constant vector -> uniform -> mean disparity
//   channels [C,2C):  sliding-window softargmax over feaR via fp32 prefix sums
//       (see derivation in earlier rounds: P=prefix(e), Q=prefix(j*e), each
//        output is O(1) from two window differences + invalid-count terms).
//
// R1: fp64 -> fp32 scan: 105us -> 10.7us (was FP64-pipe-bound).
// R4: issue-bound (issue=76%, all pipes <36%): warp-per-row restructure.
//     - one warp = one 256-wide row, 8 elems/lane, float4 LDG/STG
//     - __expf / __fdividef (MUFU fast paths)
//     - in-lane serial scan + single warp scan of totals (no block barrier)
//     - padded shared layout idx+(idx>>3): stride-8 lookups -> stride-9,
//       conflict-free (gcd(9,32)=1)

#define GC_C 32
#define GC_H 128
#define GC_W 256
#define RPB  8                  // rows per block (8 warps)
#define SPAD 292                // 256 + 256/8 = 288 used, +4 slack

__device__ __forceinline__ int pad_idx(int i) { return i + (i >> 3); }

__global__ __launch_bounds__(256)
void gcnet_softargmax_kernel(const float* __restrict__ feaR,
                             const int* __restrict__ p_min_disp,
                             const int* __restrict__ p_max_disp,
                             float* __restrict__ out)
{
    __shared__ float sP[RPB][SPAD];
    __shared__ float sQ[RPB][SPAD];

    const int lane = threadIdx.x & 31;
    const int wrp  = threadIdx.x >> 5;
    const int row  = blockIdx.x * RPB + wrp;       // row = c*H + h, 0..4095

    const int min_disp = p_min_disp ? *p_min_disp : 0;
    const int max_disp = p_max_disp ? *p_max_disp : 128;
    const int dmin = min_disp / 2;
    const int dmax = max_disp / 2;
    const int D    = dmax - dmin;
    const float meanD    = 0.5f * (float)(dmin + dmax - 1);
    const float sumAll_d = meanD * (float)D;

    // ---- load 8 contiguous elements per lane (2x float4)
    const float* rptr = feaR + (size_t)row * GC_W + lane * 8;
    const float4 v0 = *(const float4*)(rptr);
    const float4 v1 = *(const float4*)(rptr + 4);
    float e[8], q[8];
    const float xs[8] = { v0.x, v0.y, v0.z, v0.w, v1.x, v1.y, v1.z, v1.w };
    const int wbase = lane * 8;
    #pragma unroll
    for (int i = 0; i < 8; i++) {
        e[i] = __expf(xs[i]);
        q[i] = (float)(wbase + i) * e[i];
    }

    // ---- in-lane serial inclusive scan
    #pragma unroll
    for (int i = 1; i < 8; i++) { e[i] += e[i - 1]; q[i] += q[i - 1]; }

    // ---- warp exclusive scan of lane totals
    float se = e[7], sq = q[7];
    const float tot_e = se, tot_q = sq;
    #pragma unroll
    for (int off = 1; off < 32; off <<= 1) {
        float te = __shfl_up_sync(0xffffffffu, se, off);
        float tq = __shfl_up_sync(0xffffffffu, sq, off);
        if (lane >= off) { se += te; sq += tq; }
    }
    const float base_e = se - tot_e;    // exclusive prefix for this lane
    const float base_q = sq - tot_q;

    // ---- publish full-row inclusive scan to padded shared (conflict-free)
    #pragma unroll
    for (int i = 0; i < 8; i++) {
        const int pi = pad_idx(wbase + i);   // = 9*lane + i for i<8
        sP[wrp][pi] = e[i] + base_e;
        sQ[wrp][pi] = q[i] + base_q;
    }
    __syncwarp();

    // ---- per-output window math (O(1) each)
    float res[8];
    #pragma unroll
    for (int i = 0; i < 8; i++) {
        const int w = wbase + i;
        const int m = min(dmax - 1, w);          // highest valid disparity
        if (m < dmin) {
            // no valid disparity: all D entries cost 0 -> uniform -> mean
            res[i] = meanD;
        } else {
            const int hi = w - dmin;             // >= 0
            const int lo = w - m;                // >= 0
            const float ph = sP[wrp][pad_idx(hi)];
            const float qh = sQ[wrp][pad_idx(hi)];
            float pb = 0.0f, qb = 0.0f;
            if (lo > 0) {
                const int bi = pad_idx(lo - 1);
                pb = sP[wrp][bi];
                qb = sQ[wrp][bi];
            }
            const float dP = ph - pb;
            const float dQ = qh - qb;
            const int   nValid = m - dmin + 1;
            const int   nInv   = D - nValid;
            const float sumValid_d = 0.5f * (float)(m + dmin) * (float)nValid;
            const float s0 = dP + (float)nInv;
            const float s1 = (float)w * dP - dQ + (sumAll_d - sumValid_d);
            res[i] = __fdividef(s1, s0);
        }
    }

    // ---- stores (float4): left channels are the constant meanD
    float* outL = out + (size_t)row * GC_W + wbase;
    float* outR = outL + (size_t)GC_C * GC_H * GC_W;
    const float4 cst = make_float4(meanD, meanD, meanD, meanD);
    *(float4*)(outL)     = cst;
    *(float4*)(outL + 4) = cst;
    *(float4*)(outR)     = make_float4(res[0], res[1], res[2], res[3]);
    *(float4*)(outR + 4) = make_float4(res[4], res[5], res[6], res[7]);
}

extern "C" void kernel_launch(void* const* d_in, const int* in_sizes, int n_in,
                              void* d_out, int out_size)
{
    // metadata order: feaL (unused — left channels are constant), feaR, min_disp, max_disp
    const float* feaR = (const float*)d_in[1];
    const int* pmin = (n_in > 2) ? (const int*)d_in[2] : nullptr;
    const int* pmax = (n_in > 3) ? (const int*)d_in[3] : nullptr;
    float* out = (float*)d_out;

    dim3 grid((GC_C * GC_H) / RPB);   // 512 blocks, 8 rows each
    dim3 block(256);
    gcnet_softargmax_kernel<<<grid, block>>>(feaR, pmin, pmax, out);
}

// round 6
// speedup vs baseline: 15.8454x; 1.3430x over previous
#include <cuda_runtime.h>
#include <cuda_bf16.h>

// GCNet cost-volume + softargmax, specialized:
//   B=1, C=32, H=128, W=256, dmin=min_disp/2, dmax=max_disp/2 (default 0,64)
//
//   channels [0,C):   softmax over d-constant vector -> uniform -> mean disparity
//   channels [C,2C):  sliding-window softargmax over feaR via fp32 prefix sums:
//       P=prefix(e), Q=prefix(j*e); each output is O(1) from window differences.
//
// R1: fp64 -> fp32 scan: 105us -> 10.7us (FP64-pipe-bound).
// R4: warp-per-row, 8 elem/lane, smem windows: 10.7 -> 8.9us.
// R5: (a) fast path for dmin=0,D=64: P[w-64] == shfl_up(Pfull, 8 lanes) at the
//         same slot -> no shared memory, no syncwarp, unified predicated window
//         math for partial windows (lanes 0-7).
//     (b) RPB 8->4 (grid 1024): 3-vs-4 blocks/SM imbalance (33% tail) -> ~2%.
//     (c) constant left-half stores issued before compute to overlap.

#define GC_C 32
#define GC_H 128
#define GC_W 256
#define RPB  4                  // rows per block (4 warps, one per SMSP)
#define SPAD 292                // generic-path padded row: 256 + 32 + slack

__device__ __forceinline__ int pad_idx(int i) { return i + (i >> 3); }

__global__ __launch_bounds__(32 * RPB)
void gcnet_softargmax_kernel(const float* __restrict__ feaR,
                             const int* __restrict__ p_min_disp,
                             const int* __restrict__ p_max_disp,
                             float* __restrict__ out)
{
    __shared__ float sP[RPB][SPAD];   // generic fallback only
    __shared__ float sQ[RPB][SPAD];

    const int lane  = threadIdx.x & 31;
    const int wrp   = threadIdx.x >> 5;
    const int row   = blockIdx.x * RPB + wrp;      // row = c*H + h, 0..4095
    const int wbase = lane * 8;

    // ---- start the loads immediately
    const float* rptr = feaR + (size_t)row * GC_W + wbase;
    const float4 v0 = *(const float4*)(rptr);
    const float4 v1 = *(const float4*)(rptr + 4);

    const int min_disp = p_min_disp ? *p_min_disp : 0;
    const int max_disp = p_max_disp ? *p_max_disp : 128;
    const int dmin = min_disp / 2;
    const int dmax = max_disp / 2;
    const int D    = dmax - dmin;
    const float meanD    = 0.5f * (float)(dmin + dmax - 1);
    const float sumAll_d = meanD * (float)D;

    // ---- left channels: constant; fire these 4MB of stores before compute
    float* outL = out + (size_t)row * GC_W + wbase;
    const float4 cst = make_float4(meanD, meanD, meanD, meanD);
    *(float4*)(outL)     = cst;
    *(float4*)(outL + 4) = cst;

    // ---- exp + weighted values
    const float xs[8] = { v0.x, v0.y, v0.z, v0.w, v1.x, v1.y, v1.z, v1.w };
    const float fw = (float)wbase;
    float e[8], q[8];
    #pragma unroll
    for (int i = 0; i < 8; i++) {
        e[i] = __expf(xs[i]);
        q[i] = (fw + (float)i) * e[i];
    }

    // ---- in-lane serial inclusive scan
    #pragma unroll
    for (int i = 1; i < 8; i++) { e[i] += e[i - 1]; q[i] += q[i - 1]; }

    // ---- warp exclusive scan of lane totals
    float se = e[7], sq = q[7];
    const float tot_e = se, tot_q = sq;
    #pragma unroll
    for (int off = 1; off < 32; off <<= 1) {
        float te = __shfl_up_sync(0xffffffffu, se, off);
        float tq = __shfl_up_sync(0xffffffffu, sq, off);
        if (lane >= off) { se += te; sq += tq; }
    }
    const float base_e = se - tot_e;
    const float base_q = sq - tot_q;

    // ---- full inclusive prefix at each owned w (in registers)
    #pragma unroll
    for (int i = 0; i < 8; i++) { e[i] += base_e; q[i] += base_q; }

    float res[8];

    if (dmin == 0 && D == 64) {
        // ===== fast path: window start w-64 is exactly 8 lanes back, same slot
        #pragma unroll
        for (int i = 0; i < 8; i++) {
            const int   w  = wbase + i;
            const float pbu = __shfl_up_sync(0xffffffffu, e[i], 8);
            const float qbu = __shfl_up_sync(0xffffffffu, q[i], 8);
            const float pb = (lane >= 8) ? pbu : 0.0f;
            const float qb = (lane >= 8) ? qbu : 0.0f;
            const int   m  = min(63, w);               // highest valid disparity
            const float fInv = (float)(63 - m);        // invalid count (exp(0)=1 each)
            const float corr = 2016.0f - 0.5f * (float)(m * (m + 1)); // sumAll_d - sumValid_d
            const float dP = e[i] - pb;
            const float dQ = q[i] - qb;
            const float s0 = dP + fInv;
            const float s1 = (float)w * dP - dQ + corr;
            res[i] = __fdividef(s1, s0);
        }
    } else {
        // ===== generic fallback (arbitrary dmin/dmax): padded shared lookups
        #pragma unroll
        for (int i = 0; i < 8; i++) {
            const int pi = pad_idx(wbase + i);
            sP[wrp][pi] = e[i];
            sQ[wrp][pi] = q[i];
        }
        __syncwarp();
        #pragma unroll
        for (int i = 0; i < 8; i++) {
            const int w = wbase + i;
            const int m = min(dmax - 1, w);
            if (m < dmin) {
                res[i] = meanD;      // no valid disparity: uniform -> mean
            } else {
                const int hi = w - dmin;
                const int lo = w - m;
                const float ph = sP[wrp][pad_idx(hi)];
                const float qh = sQ[wrp][pad_idx(hi)];
                float pb = 0.0f, qb = 0.0f;
                if (lo > 0) {
                    const int bi = pad_idx(lo - 1);
                    pb = sP[wrp][bi];
                    qb = sQ[wrp][bi];
                }
                const float dP = ph - pb;
                const float dQ = qh - qb;
                const int   nValid = m - dmin + 1;
                const int   nInv   = D - nValid;
                const float sumValid_d = 0.5f * (float)(m + dmin) * (float)nValid;
                const float s0 = dP + (float)nInv;
                const float s1 = (float)w * dP - dQ + (sumAll_d - sumValid_d);
                res[i] = __fdividef(s1, s0);
            }
        }
    }

    // ---- right-channel stores
    float* outR = outL + (size_t)GC_C * GC_H * GC_W;
    *(float4*)(outR)     = make_float4(res[0], res[1], res[2], res[3]);
    *(float4*)(outR + 4) = make_float4(res[4], res[5], res[6], res[7]);
}

extern "C" void kernel_launch(void* const* d_in, const int* in_sizes, int n_in,
                              void* d_out, int out_size)
{
    // metadata order: feaL (unused — left channels are constant), feaR, min_disp, max_disp
    const float* feaR = (const float*)d_in[1];
    const int* pmin = (n_in > 2) ? (const int*)d_in[2] : nullptr;
    const int* pmax = (n_in > 3) ? (const int*)d_in[3] : nullptr;
    float* out = (float*)d_out;

    dim3 grid((GC_C * GC_H) / RPB);   // 1024 blocks, 4 rows each
    dim3 block(32 * RPB);
    gcnet_softargmax_kernel<<<grid, block>>>(feaR, pmin, pmax, out);
}